// round 10
// baseline (speedup 1.0000x reference)
#include <cuda_runtime.h>
#include <cstdint>

#define NCLS   10
#define NB     32
#define NBINS  (NB * NCLS)      // 320
#define NATOMS 16384
#define DIN    272
#define HID    64
#define NOUT   128
#define L0OUT  256
#define IN0    32
#define ATILE  32               // atoms per tile
#define BINCAP 512
#define NT     256
#define PADA   36               // s1 row stride (floats)

// static device scratch (module-init zero; replay-safe lifecycle below)
__device__ int g_cnt[NBINS];
__device__ int g_list[NBINS * BINCAP];

__device__ __forceinline__ float silu_f(float x) {
    return x * (1.0f / (1.0f + __expf(-x)));
}

// packed dual-fp32 FMA: d.lo += a.lo*b.lo ; d.hi += a.hi*b.hi
__device__ __forceinline__ void ffma2(unsigned long long& d,
                                      unsigned long long a,
                                      unsigned long long b) {
    asm("fma.rn.f32x2 %0, %1, %2, %0;" : "+l"(d) : "l"(a), "l"(b));
}
__device__ __forceinline__ unsigned long long pack2(float x) {
    unsigned long long r;
    asm("mov.b64 %0, {%1, %1};" : "=l"(r) : "f"(x));
    return r;
}
__device__ __forceinline__ float lo32(unsigned long long v) {
    return __uint_as_float((unsigned)(v & 0xffffffffull));
}
__device__ __forceinline__ float hi32(unsigned long long v) {
    return __uint_as_float((unsigned)(v >> 32));
}

// ===========================================================================
// Kernel A: warp-aggregated counting-sort into 320 (b, cls) bins
// ===========================================================================
__global__ __launch_bounds__(128) void classify_kernel(
    const int* __restrict__ mapping)
{
    int gtid = blockIdx.x * 128 + threadIdx.x;      // 0..16383
    int m = mapping[gtid];
    int b = gtid >> 9;                              // batch (warp-uniform)
    int bin = b * NCLS + m;
    unsigned peers  = __match_any_sync(0xffffffffu, m);
    int lane   = threadIdx.x & 31;
    int leader = __ffs(peers) - 1;
    int rank   = __popc(peers & ((1u << lane) - 1u));
    int base   = 0;
    if (m < NCLS && lane == leader)
        base = atomicAdd(&g_cnt[bin], __popc(peers));
    base = __shfl_sync(0xffffffffu, base, leader);
    if (m < NCLS) g_list[bin * BINCAP + base + rank] = gtid;
}

// ===========================================================================
// Kernel B: one block per (b, cls) bin, 256 threads, 4 CTAs/SM.
// Software-pipelined: tile gathers are speculative (always in-bounds — stale
// g_list entries are valid atom ids; the cnt mask applies at the smem store),
// issued one tile ahead so LDG latency never sits on the barrier path.
// ===========================================================================
__global__ __launch_bounds__(NT, 4) void mlp_kernel(
    const float* __restrict__ af,      // (16384, 272)
    const float* __restrict__ W0,      // (T, 32, 256)
    const float* __restrict__ W1,      // (T, 64, 256)
    const float* __restrict__ Wo,      // (T, 64, 128)
    float*       __restrict__ out)     // (NB, T*128)
{
    __shared__ float WaN[IN0 * HID];       // [k][o] natural   8KB
    __shared__ float WbN[HID * HID];       // [k][o] natural  16KB
    __shared__ float xs[2][IN0 * ATILE];   // [k][a] x2        8KB
    __shared__ float s1[HID * PADA];       // [k][a] padded    9KB
    __shared__ int   s_cnt;

    const int t   = threadIdx.x;
    const int bin = blockIdx.x;
    const int b   = bin / NCLS;
    const int cls = bin % NCLS;

    // ---------------- parallel prologue: all loads independent -------------
    if (t == 0) {                          // race-safe read+reset, sole reader
        s_cnt = __ldcg(&g_cnt[bin]);
        g_cnt[bin] = 0;
    }

    const int a = t >> 3;                  // atom slot 0..31
    const int q = t & 7;                   // feature quarter (4 floats)

    // speculative tile-0 gather (unmasked; mask applied at store)
    int   id0 = __ldcg(&g_list[bin * BINCAP + a]);
    float4 f0 = __ldg((const float4*)(af + (size_t)id0 * DIN + q * 4));

    // weights (live 64 cols of 256)
    const float4* w0p = (const float4*)(W0 + (size_t)cls * IN0 * L0OUT);
    const float4* w1p = (const float4*)(W1 + (size_t)cls * HID * L0OUT);
    float4 w0r[2], w1r[4];
    #pragma unroll
    for (int r = 0; r < 2; r++) {
        int idx = r * NT + t;
        w0r[r] = __ldg(&w0p[(idx >> 4) * 64 + (idx & 15)]);
    }
    #pragma unroll
    for (int r = 0; r < 4; r++) {
        int idx = r * NT + t;
        w1r[r] = __ldg(&w1p[(idx >> 4) * 64 + (idx & 15)]);
    }

    __syncthreads();                       // s_cnt visible
    const int cnt    = s_cnt;
    const int ntiles = (cnt + ATILE - 1) >> 5;

    // stage weights + masked tile-0 store
    #pragma unroll
    for (int r = 0; r < 2; r++) {
        int idx = r * NT + t;
        ((float4*)WaN)[(idx >> 4) * 16 + (idx & 15)] = w0r[r];
    }
    #pragma unroll
    for (int r = 0; r < 4; r++) {
        int idx = r * NT + t;
        ((float4*)WbN)[(idx >> 4) * 16 + (idx & 15)] = w1r[r];
    }
    {
        float4 v = (a < cnt) ? f0 : make_float4(0.f, 0.f, 0.f, 0.f);
        int kb = q * 4;
        xs[0][(kb + 0) * ATILE + a] = v.x;
        xs[0][(kb + 1) * ATILE + a] = v.y;
        xs[0][(kb + 2) * ATILE + a] = v.z;
        xs[0][(kb + 3) * ATILE + a] = v.w;
    }
    __syncthreads();

    // micro-tile: 2 atoms x 4 outputs (2 o-pairs) per thread
    const int a0 = (t & 15) << 1;
    const int o0 = (t >> 4) << 2;
    const float RS32 = 0.17677669529663687f;   // 1/sqrt(32)
    float part[4] = {0.f, 0.f, 0.f, 0.f};

    for (int i = 0; i < ntiles; i++) {
        const int buf = i & 1;

        // ---- issue prefetch for tile i+1 (speculative, in-bounds) ----
        float4 pf = make_float4(0.f, 0.f, 0.f, 0.f);
        bool have_pf = (i + 1 < ntiles);
        if (have_pf) {
            int idn = __ldcg(&g_list[bin * BINCAP + (i + 1) * ATILE + a]);
            pf = __ldg((const float4*)(af + (size_t)idn * DIN + q * 4));
        }

        // ---- stage 1: [32a x 32k x 64o], o-paired FFMA2 ----
        unsigned long long acc1[2][2] = {};
        #pragma unroll
        for (int k = 0; k < IN0; k++) {
            float2 xv = *(const float2*)&xs[buf][k * ATILE + a0];
            ulonglong2 wv = *(const ulonglong2*)&WaN[k * HID + o0];
            unsigned long long x0 = pack2(xv.x), x1 = pack2(xv.y);
            ffma2(acc1[0][0], x0, wv.x);
            ffma2(acc1[0][1], x0, wv.y);
            ffma2(acc1[1][0], x1, wv.x);
            ffma2(acc1[1][1], x1, wv.y);
        }
        #pragma unroll
        for (int p = 0; p < 2; p++) {          // silu + transposed store
            float2 vlo, vhi;
            vlo.x = silu_f(lo32(acc1[0][p]) * RS32);
            vlo.y = silu_f(lo32(acc1[1][p]) * RS32);
            vhi.x = silu_f(hi32(acc1[0][p]) * RS32);
            vhi.y = silu_f(hi32(acc1[1][p]) * RS32);
            *(float2*)&s1[(o0 + 2 * p)     * PADA + a0] = vlo;
            *(float2*)&s1[(o0 + 2 * p + 1) * PADA + a0] = vhi;
        }
        __syncthreads();                       // s1 ready

        // ---- stage 2: [32a x 64k x 64o]; pads are exact zeros ----
        unsigned long long acc2[2][2] = {};
        #pragma unroll
        for (int k = 0; k < HID; k++) {
            float2 xv = *(const float2*)&s1[k * PADA + a0];
            ulonglong2 wv = *(const ulonglong2*)&WbN[k * HID + o0];
            unsigned long long x0 = pack2(xv.x), x1 = pack2(xv.y);
            ffma2(acc2[0][0], x0, wv.x);
            ffma2(acc2[0][1], x0, wv.y);
            ffma2(acc2[1][0], x1, wv.x);
            ffma2(acc2[1][1], x1, wv.y);
        }
        #pragma unroll
        for (int p = 0; p < 2; p++) {
            part[2 * p]     += silu_f(lo32(acc2[0][p]) * 0.125f)
                             + silu_f(lo32(acc2[1][p]) * 0.125f);
            part[2 * p + 1] += silu_f(hi32(acc2[0][p]) * 0.125f)
                             + silu_f(hi32(acc2[1][p]) * 0.125f);
        }

        // ---- store prefetched tile i+1 into the other buffer ----
        if (have_pf) {
            float4 v = ((i + 1) * ATILE + a < cnt)
                     ? pf : make_float4(0.f, 0.f, 0.f, 0.f);
            int kb = q * 4;
            xs[buf ^ 1][(kb + 0) * ATILE + a] = v.x;
            xs[buf ^ 1][(kb + 1) * ATILE + a] = v.y;
            xs[buf ^ 1][(kb + 2) * ATILE + a] = v.z;
            xs[buf ^ 1][(kb + 3) * ATILE + a] = v.w;
        }
        __syncthreads();                       // s1 free + xs[buf^1] ready
    }

    // ===== reduce part[] over the 16 atom-groups (warp bits 0-3) =====
    #pragma unroll
    for (int off = 1; off < 16; off <<= 1)
        #pragma unroll
        for (int j = 0; j < 4; j++)
            part[j] += __shfl_xor_sync(0xffffffffu, part[j], off);

    float* red = xs[0];        // alias: xs dead now
    __syncthreads();
    if ((t & 15) == 0) {
        #pragma unroll
        for (int j = 0; j < 4; j++) red[o0 + j] = part[j];
    }
    __syncthreads();

    // ===== final: out[b, cls*128 + o] = (red @ Wout[cls])[o] / 8 =====
    if (t < NOUT) {
        const float* wp = Wo + (size_t)cls * HID * NOUT + t;
        float s = 0.0f;
        #pragma unroll
        for (int h = 0; h < HID; h++)
            s += red[h] * __ldg(&wp[h * NOUT]);
        out[b * (NCLS * NOUT) + cls * NOUT + t] = 0.125f * s;
    }
}

// ---------------------------------------------------------------------------
extern "C" void kernel_launch(void* const* d_in, const int* in_sizes, int n_in,
                              void* d_out, int out_size) {
    const float* af      = (const float*)d_in[0];   // atom_features
    const float* W0      = (const float*)d_in[1];   // W0_0
    const float* W1      = (const float*)d_in[5];   // W1_0
    const float* Wo      = (const float*)d_in[9];   // Wout
    const int*   mapping = (const int*)  d_in[10];  // mlp_mapping
    float* out = (float*)d_out;

    classify_kernel<<<NATOMS / 128, 128>>>(mapping);
    mlp_kernel<<<NBINS, NT>>>(af, W0, W1, Wo, out);
}